// round 6
// baseline (speedup 1.0000x reference)
#include <cuda_runtime.h>
#include <cstddef>

#define Bq 256
#define Sq 4096
#define Hq 64
#define Cq 32            // chunks along S
#define Lq (Sq / Cq)     // 128 elements per chunk

// Per-(b,chunk,h) chunk aggregates -> (after k_prefix) exclusive prefixes. 2 MB, L2-resident.
__device__ __align__(16) float g_part[(size_t)Bq * Cq * Hq];

typedef unsigned long long u64;

__device__ __forceinline__ u64 pack2(float lo, float hi) {
    u64 r; asm("mov.b64 %0, {%1, %2};" : "=l"(r) : "f"(lo), "f"(hi)); return r;
}
__device__ __forceinline__ void unpack2(u64 v, float& lo, float& hi) {
    asm("mov.b64 {%0, %1}, %2;" : "=f"(lo), "=f"(hi) : "l"(v));
}
__device__ __forceinline__ u64 fma2(u64 a, u64 b, u64 c) {
    u64 d; asm("fma.rn.f32x2 %0, %1, %2, %3;" : "=l"(d) : "l"(a), "l"(b), "l"(c)); return d;
}
__device__ __forceinline__ u64 add2(u64 a, u64 b) {
    u64 d; asm("add.rn.f32x2 %0, %1, %2;" : "=l"(d) : "l"(a), "l"(b)); return d;
}

#define MAGIC 12582912.0f   // 1.5*2^23: (u+MAGIC)-MAGIC == rint(u) for |u| < 2^22

// ---------------- Phase 1: chunk aggregates via separability ----------------
__global__ void __launch_bounds__(128) k_partials(const float* __restrict__ x,
                                                  const float* __restrict__ W_e,
                                                  const float* __restrict__ b_e,
                                                  const float* __restrict__ omega) {
    __shared__ float2 shx[2][Lq / 2];
    __shared__ float  s_red[4];
    const int t  = threadIdx.x;
    const int g  = t >> 6;              // chunk group 0..1
    const int h  = t & 63;
    const int bc = blockIdx.x * 2 + g;  // b*Cq + c
    const int b  = bc >> 5;

    const float2* xc = (const float2*)(x + (size_t)b * Sq + (size_t)(bc & 31) * Lq);
    float2 v = __ldg(xc + h);
    shx[g][h] = v;

    const float INV_2PI = 0.15915494309189535f;
    const float TWO_PI  = 6.283185307179586f;
    const float we2 = W_e[h]   * INV_2PI;
    const float be2 = b_e[h]   * INV_2PI;
    const float om2 = omega[h] * TWO_PI;

    float ps = v.x + v.y;
#pragma unroll
    for (int o = 16; o > 0; o >>= 1) ps += __shfl_down_sync(0xffffffffu, ps, o);
    if ((t & 31) == 0) s_red[t >> 5] = ps;
    __syncthreads();
    const float sx = s_red[2 * g] + s_red[2 * g + 1];

    const u64 we2p  = pack2(we2, we2);
    const u64 be2p  = pack2(be2, be2);
    const u64 Mp    = pack2(MAGIC, MAGIC);
    const u64 negMp = pack2(-MAGIC, -MAGIC);
    u64 racc2 = 0ull;
#pragma unroll 16
    for (int i = 0; i < Lq / 2; ++i) {
        float2 xv = shx[g][i];
        u64 u2 = fma2(pack2(xv.x, xv.y), we2p, be2p);
        u64 k2 = add2(add2(u2, Mp), negMp);
        racc2 = add2(racc2, k2);
    }
    float rlo, rhi; unpack2(racc2, rlo, rhi);
    g_part[(size_t)bc * Hq + h] = om2 * (fmaf(we2, sx, (float)Lq * be2) - (rlo + rhi));
}

// ---------------- Phase 1.5: in-place exclusive prefix over chunks ----------------
__global__ void k_prefix() {
    int t = blockIdx.x * blockDim.x + threadIdx.x;  // 16384 threads: (b,h)
    int b = t >> 6, h = t & 63;
    float* p = g_part + (size_t)(b << 5) * Hq + h;
    float run = 0.0f;
#pragma unroll
    for (int c = 0; c < Cq; ++c) {
        float v = p[(size_t)c * Hq];
        p[(size_t)c * Hq] = run;
        run += v;
    }
}

// ---------------- Phase 2: scan. 1 warp/block = 2 chunks; 4 channels/lane; STG.128 ----------------
__global__ void __launch_bounds__(32) k_scan(const float* __restrict__ x,
                                             const float* __restrict__ W_e,
                                             const float* __restrict__ b_e,
                                             const float* __restrict__ omega,
                                             const float* __restrict__ W_r,
                                             const float* __restrict__ b_r,
                                             float* __restrict__ out,
                                             float* __restrict__ hseq) {
    __shared__ float2 shx[2 * Lq];      // 2 chunks of x, duplicated {x,x}
    const int l  = threadIdx.x;
    const int q  = blockIdx.x;          // chunk-pair id: chunks {2q, 2q+1}
    const int b  = q >> 4;
    const int c0 = (q & 15) << 1;

    // Stage 256 contiguous floats (2 chunks), duplicate for LDS.64 broadcast.
    const float4* xg = (const float4*)(x + (size_t)b * Sq + (size_t)c0 * Lq);
    float4 v0 = __ldg(xg + l);
    float4 v1 = __ldg(xg + 32 + l);
    int i0 = 4 * l;
    shx[i0 + 0] = make_float2(v0.x, v0.x);
    shx[i0 + 1] = make_float2(v0.y, v0.y);
    shx[i0 + 2] = make_float2(v0.z, v0.z);
    shx[i0 + 3] = make_float2(v0.w, v0.w);
    shx[128 + i0 + 0] = make_float2(v1.x, v1.x);
    shx[128 + i0 + 1] = make_float2(v1.y, v1.y);
    shx[128 + i0 + 2] = make_float2(v1.z, v1.z);
    shx[128 + i0 + 3] = make_float2(v1.w, v1.w);

    const int half = l >> 4;            // which chunk of the pair
    const int h0   = (l & 15) << 2;     // 4 channels per lane
    const int c    = c0 + half;

    const float INV_2PI = 0.15915494309189535f;
    const float TWO_PI  = 6.283185307179586f;
    const u64 we2a = pack2(W_e[h0]     * INV_2PI, W_e[h0 + 1]   * INV_2PI);
    const u64 we2b = pack2(W_e[h0 + 2] * INV_2PI, W_e[h0 + 3]   * INV_2PI);
    const u64 be2a = pack2(b_e[h0]     * INV_2PI, b_e[h0 + 1]   * INV_2PI);
    const u64 be2b = pack2(b_e[h0 + 2] * INV_2PI, b_e[h0 + 3]   * INV_2PI);
    const u64 om2a = pack2(omega[h0]     * TWO_PI, omega[h0 + 1] * TWO_PI);
    const u64 om2b = pack2(omega[h0 + 2] * TWO_PI, omega[h0 + 3] * TWO_PI);
    const u64 Mp    = pack2(MAGIC, MAGIC);
    const u64 negMp = pack2(-MAGIC, -MAGIC);
    const u64 nOne  = pack2(-1.0f, -1.0f);

    // Carry: single float4 (exclusive prefix from k_prefix).
    float4 cp = __ldg((const float4*)(g_part + ((size_t)(b << 5) + c) * Hq + h0));
    u64 acc2a = pack2(cp.x, cp.y);
    u64 acc2b = pack2(cp.z, cp.w);
    __syncwarp();

    const u64* xs = (const u64*)(shx + half * Lq);
    char* hp = (char*)(hseq + ((size_t)b * Sq + (size_t)c * Lq) * Hq + h0);
#pragma unroll 8
    for (int s = 0; s < Lq; ++s) {
        u64 x2 = xs[s];                                 // LDS.64 broadcast
        u64 ua = fma2(x2, we2a, be2a);
        u64 ka = add2(add2(ua, Mp), negMp);             // rint, exact
        acc2a  = fma2(om2a, fma2(ka, nOne, ua), acc2a); // += om*(u-k)
        u64 ub = fma2(x2, we2b, be2b);
        u64 kb = add2(add2(ub, Mp), negMp);
        acc2b  = fma2(om2b, fma2(kb, nOne, ub), acc2b);
        ulonglong2 stv; stv.x = acc2a; stv.y = acc2b;
        *(ulonglong2*)(hp + (size_t)s * (Hq * 4)) = stv; // plain STG.128 (cached: L2 re-dirty)
    }

    // Output head: chunk 31's final accumulators are ph[b][h0..h0+3].
    if (c == Cq - 1) {
        float p0, p1, p2, p3;
        unpack2(acc2a, p0, p1);
        unpack2(acc2b, p2, p3);
        float tv;
        tv = p0 * W_r[2 * Hq + h0];
        tv = fmaf(cosf(p0), W_r[h0], tv);
        tv = fmaf(sinf(p0), W_r[Hq + h0], tv);
        tv = fmaf(p1, W_r[2 * Hq + h0 + 1], tv);
        tv = fmaf(cosf(p1), W_r[h0 + 1], tv);
        tv = fmaf(sinf(p1), W_r[Hq + h0 + 1], tv);
        tv = fmaf(p2, W_r[2 * Hq + h0 + 2], tv);
        tv = fmaf(cosf(p2), W_r[h0 + 2], tv);
        tv = fmaf(sinf(p2), W_r[Hq + h0 + 2], tv);
        tv = fmaf(p3, W_r[2 * Hq + h0 + 3], tv);
        tv = fmaf(cosf(p3), W_r[h0 + 3], tv);
        tv = fmaf(sinf(p3), W_r[Hq + h0 + 3], tv);
#pragma unroll
        for (int o = 8; o > 0; o >>= 1)
            tv += __shfl_down_sync(0xFFFF0000u, tv, o, 16);
        if (l == 16) out[b] = tv + b_r[0];
    }
}

extern "C" void kernel_launch(void* const* d_in, const int* in_sizes, int n_in,
                              void* d_out, int out_size) {
    const float* x     = (const float*)d_in[0];
    const float* W_e   = (const float*)d_in[1];
    const float* b_e   = (const float*)d_in[2];
    const float* omega = (const float*)d_in[3];
    const float* W_r   = (const float*)d_in[4];
    const float* b_r   = (const float*)d_in[5];

    float* out  = (float*)d_out;        // out = B floats
    float* hseq = (float*)d_out + Bq;   // then Hseq = B*S*H floats

    k_partials<<<(Bq * Cq) / 2, 128>>>(x, W_e, b_e, omega);
    k_prefix<<<(Bq * Hq) / 256, 256>>>();
    k_scan<<<(Bq * Cq) / 2, 32>>>(x, W_e, b_e, omega, W_r, b_r, out, hseq);
}

// round 7
// speedup vs baseline: 1.1928x; 1.1928x over previous
#include <cuda_runtime.h>
#include <cstddef>

#define Bq 256
#define Sq 4096
#define Hq 64
#define Cq 32            // chunks along S
#define Lq (Sq / Cq)     // 128 elements per chunk

// Per-(b,chunk,h) chunk aggregates. 2 MB, L2-resident.
__device__ __align__(16) float g_part[(size_t)Bq * Cq * Hq];
// Per-row completion counters (reset by memset each launch).
__device__ unsigned g_rowcnt[Bq];

typedef unsigned long long u64;

__device__ __forceinline__ u64 pack2(float lo, float hi) {
    u64 r; asm("mov.b64 %0, {%1, %2};" : "=l"(r) : "f"(lo), "f"(hi)); return r;
}
__device__ __forceinline__ void unpack2(u64 v, float& lo, float& hi) {
    asm("mov.b64 {%0, %1}, %2;" : "=f"(lo), "=f"(hi) : "l"(v));
}
__device__ __forceinline__ u64 fma2(u64 a, u64 b, u64 c) {
    u64 d; asm("fma.rn.f32x2 %0, %1, %2, %3;" : "=l"(d) : "l"(a), "l"(b), "l"(c)); return d;
}
__device__ __forceinline__ u64 add2(u64 a, u64 b) {
    u64 d; asm("add.rn.f32x2 %0, %1, %2;" : "=l"(d) : "l"(a), "l"(b)); return d;
}

#define MAGIC 12582912.0f   // 1.5*2^23: (u+MAGIC)-MAGIC == rint(u) for |u| < 2^22

// One fused kernel. Block = 64 threads = 2 warps; warp g owns chunk c0+g.
// Lane l owns channels h = 2l, 2l+1 (packed f32x2) for BOTH pass 1 and pass 2.
__global__ void __launch_bounds__(Hq) k_fused(const float* __restrict__ x,
                                              const float* __restrict__ W_e,
                                              const float* __restrict__ b_e,
                                              const float* __restrict__ omega,
                                              const float* __restrict__ W_r,
                                              const float* __restrict__ b_r,
                                              float* __restrict__ out,
                                              float* __restrict__ hseq) {
    __shared__ float2 shx[2 * Lq];      // 2 chunks of x, duplicated {x,x}
    const int t  = threadIdx.x;
    const int g  = t >> 5;              // warp -> chunk within pair
    const int l  = t & 31;
    const int q  = blockIdx.x;          // chunk-pair id
    const int b  = q >> 4;
    const int c0 = (q & 15) << 1;
    const int c  = c0 + g;
    const int h0 = 2 * l;

    // ---- stage 256 contiguous floats (2 chunks), duplicated for LDS.64 broadcast ----
    {
        const float4* xg = (const float4*)(x + (size_t)b * Sq + (size_t)c0 * Lq);
        float4 v = __ldg(xg + t);       // t = 0..63 covers 256 floats
        int i0 = 4 * t;
        shx[i0 + 0] = make_float2(v.x, v.x);
        shx[i0 + 1] = make_float2(v.y, v.y);
        shx[i0 + 2] = make_float2(v.z, v.z);
        shx[i0 + 3] = make_float2(v.w, v.w);
    }

    const float INV_2PI = 0.15915494309189535f;
    const float TWO_PI  = 6.283185307179586f;
    const float we_lo = W_e[h0] * INV_2PI,  we_hi = W_e[h0 + 1] * INV_2PI;
    const float be_lo = b_e[h0] * INV_2PI,  be_hi = b_e[h0 + 1] * INV_2PI;
    const u64 we2p  = pack2(we_lo, we_hi);
    const u64 be2p  = pack2(be_lo, be_hi);
    const u64 om2p  = pack2(omega[h0] * TWO_PI, omega[h0 + 1] * TWO_PI);
    const u64 beLp  = pack2((float)Lq * be_lo, (float)Lq * be_hi);
    const u64 Mp    = pack2(MAGIC, MAGIC);
    const u64 negMp = pack2(-MAGIC, -MAGIC);
    const u64 nOne  = pack2(-1.0f, -1.0f);
    __syncthreads();

    // ---- pass 1: own chunk aggregate via separability (packed 2 channels) ----
    const u64* xs = (const u64*)(shx + g * Lq);
    {
        // Sum(x) over the chunk: lane sums its 4 s-values, warp xor-reduce.
        float ps = 0.0f;
#pragma unroll
        for (int j = 0; j < 4; ++j) {
            float lo, hi; unpack2(xs[4 * l + j], lo, hi);
            ps += lo;
        }
#pragma unroll
        for (int o = 16; o > 0; o >>= 1) ps += __shfl_xor_sync(0xffffffffu, ps, o);

        u64 racc2 = 0ull;
#pragma unroll 16
        for (int s = 0; s < Lq; ++s) {
            u64 u2 = fma2(xs[s], we2p, be2p);
            racc2 = add2(racc2, add2(add2(u2, Mp), negMp));   // += rint(u), exact
        }
        // agg = om2 * (we2*sx + L*be2 - racc)
        u64 t1 = fma2(we2p, pack2(ps, ps), beLp);
        u64 t2 = fma2(racc2, nOne, t1);
        u64 agg2 = fma2(om2p, t2, 0ull);
        *(u64*)(g_part + ((size_t)(b << 5) + c) * Hq + h0) = agg2;
    }
    __syncthreads();

    // ---- shallow per-row barrier: publish, then wait for all 16 blocks of row b ----
    if (t == 0)
        asm volatile("red.release.gpu.global.add.u32 [%0], %1;"
                     :: "l"(&g_rowcnt[b]), "r"(1u) : "memory");
    if (t == 0) {
        unsigned v;
        do {
            asm volatile("ld.global.acquire.gpu.u32 %0, [%1];"
                         : "=r"(v) : "l"(&g_rowcnt[b]) : "memory");
            if (v >= 16u) break;
            __nanosleep(40);
        } while (true);
    }
    __syncthreads();

    // ---- carry: ascending sum of preceding chunk aggregates (L2-resident) ----
    float a0 = 0.f, a1 = 0.f;
    const float2* gp = (const float2*)(g_part + (size_t)(b << 5) * Hq + h0);
    for (int cc = 0; cc < c; ++cc) {
        float2 v = __ldg(gp + cc * (Hq / 2));
        a0 += v.x; a1 += v.y;
    }
    u64 acc2 = pack2(a0, a1);

    // ---- pass 2: carry-seeded scan, 2 channels/lane, STG.64 streaming ----
    char* hp = (char*)(hseq + ((size_t)b * Sq + (size_t)c * Lq) * Hq + h0);
#pragma unroll 8
    for (int s = 0; s < Lq; ++s) {
        u64 x2 = xs[s];                             // LDS.64 broadcast {x,x}
        u64 u2 = fma2(x2, we2p, be2p);
        u64 k2 = add2(add2(u2, Mp), negMp);         // rint(u), exact
        u64 f2 = fma2(k2, nOne, u2);                // u - k (exact subtract)
        acc2 = fma2(om2p, f2, acc2);
        __stcs((long long*)(hp + (size_t)s * (Hq * 4)), (long long)acc2);
    }

    // ---- output head: chunk 31's final accumulators are ph[b][h0], ph[b][h0+1] ----
    if (c == Cq - 1) {
        float p0, p1; unpack2(acc2, p0, p1);
        float tv;
        tv = p0 * W_r[2 * Hq + h0];
        tv = fmaf(cosf(p0), W_r[h0], tv);
        tv = fmaf(sinf(p0), W_r[Hq + h0], tv);
        tv = fmaf(p1, W_r[2 * Hq + h0 + 1], tv);
        tv = fmaf(cosf(p1), W_r[h0 + 1], tv);
        tv = fmaf(sinf(p1), W_r[Hq + h0 + 1], tv);
#pragma unroll
        for (int o = 16; o > 0; o >>= 1)
            tv += __shfl_down_sync(0xffffffffu, tv, o);
        if (l == 0) out[b] = tv + b_r[0];
    }
}

extern "C" void kernel_launch(void* const* d_in, const int* in_sizes, int n_in,
                              void* d_out, int out_size) {
    const float* x     = (const float*)d_in[0];
    const float* W_e   = (const float*)d_in[1];
    const float* b_e   = (const float*)d_in[2];
    const float* omega = (const float*)d_in[3];
    const float* W_r   = (const float*)d_in[4];
    const float* b_r   = (const float*)d_in[5];

    float* out  = (float*)d_out;        // out = B floats
    float* hseq = (float*)d_out + Bq;   // then Hseq = B*S*H floats

    // Reset per-row counters (1 KB, graph-capturable).
    unsigned* cnt = nullptr;
    cudaGetSymbolAddress((void**)&cnt, g_rowcnt);
    cudaMemsetAsync(cnt, 0, sizeof(unsigned) * Bq);

    k_fused<<<(Bq * Cq) / 2, Hq>>>(x, W_e, b_e, omega, W_r, b_r, out, hseq);
}

// round 8
// speedup vs baseline: 1.1935x; 1.0006x over previous
#include <cuda_runtime.h>
#include <cstddef>

#define Bq 256
#define Sq 4096
#define Hq 64
#define Cq 32            // chunks along S
#define Lq (Sq / Cq)     // 128 elements per chunk
#define CPB 4            // chunks per block (1 per warp)
#define BPR (Cq / CPB)   // blocks per row = 8

// Per-(b,chunk,h) chunk aggregates. 2 MB, L2-resident.
__device__ __align__(16) float g_part[(size_t)Bq * Cq * Hq];
// Self-resetting per-row barrier counters (zero-init at module load; each
// launch leaves them at zero again).
__device__ unsigned g_arrive[Bq];
__device__ unsigned g_depart[Bq];

typedef unsigned long long u64;

__device__ __forceinline__ u64 pack2(float lo, float hi) {
    u64 r; asm("mov.b64 %0, {%1, %2};" : "=l"(r) : "f"(lo), "f"(hi)); return r;
}
__device__ __forceinline__ void unpack2(u64 v, float& lo, float& hi) {
    asm("mov.b64 {%0, %1}, %2;" : "=f"(lo), "=f"(hi) : "l"(v));
}
__device__ __forceinline__ u64 fma2(u64 a, u64 b, u64 c) {
    u64 d; asm("fma.rn.f32x2 %0, %1, %2, %3;" : "=l"(d) : "l"(a), "l"(b), "l"(c)); return d;
}
__device__ __forceinline__ u64 add2(u64 a, u64 b) {
    u64 d; asm("add.rn.f32x2 %0, %1, %2;" : "=l"(d) : "l"(a), "l"(b)); return d;
}

#define MAGIC 12582912.0f   // 1.5*2^23: (u+MAGIC)-MAGIC == rint(u) for |u| < 2^22

// One fused kernel. Block = 128 threads = 4 warps; warp w owns chunk c0+w.
// Lane l owns channels h = 2l, 2l+1 (packed f32x2) in both passes.
__global__ void __launch_bounds__(128) k_fused(const float* __restrict__ x,
                                               const float* __restrict__ W_e,
                                               const float* __restrict__ b_e,
                                               const float* __restrict__ omega,
                                               const float* __restrict__ W_r,
                                               const float* __restrict__ b_r,
                                               float* __restrict__ out,
                                               float* __restrict__ hseq) {
    __shared__ float2 shx[CPB * Lq];    // 4 chunks of x, duplicated {x,x}
    const int t  = threadIdx.x;
    const int w  = t >> 5;              // warp -> chunk within quad
    const int l  = t & 31;
    const int q  = blockIdx.x;
    const int b  = q >> 3;
    const int c0 = (q & (BPR - 1)) * CPB;
    const int c  = c0 + w;
    const int h0 = 2 * l;

    // ---- stage 512 contiguous floats (4 chunks), duplicated for LDS.64 broadcast ----
    {
        const float4* xg = (const float4*)(x + (size_t)b * Sq + (size_t)c0 * Lq);
        float4 v = __ldg(xg + t);       // t = 0..127 covers 512 floats
        int i0 = 4 * t;
        shx[i0 + 0] = make_float2(v.x, v.x);
        shx[i0 + 1] = make_float2(v.y, v.y);
        shx[i0 + 2] = make_float2(v.z, v.z);
        shx[i0 + 3] = make_float2(v.w, v.w);
    }

    const float INV_2PI = 0.15915494309189535f;
    const float TWO_PI  = 6.283185307179586f;
    const float we_lo = W_e[h0] * INV_2PI,  we_hi = W_e[h0 + 1] * INV_2PI;
    const float be_lo = b_e[h0] * INV_2PI,  be_hi = b_e[h0 + 1] * INV_2PI;
    const u64 we2p  = pack2(we_lo, we_hi);
    const u64 be2p  = pack2(be_lo, be_hi);
    const u64 om2p  = pack2(omega[h0] * TWO_PI, omega[h0 + 1] * TWO_PI);
    const u64 beLp  = pack2((float)Lq * be_lo, (float)Lq * be_hi);
    const u64 Mp    = pack2(MAGIC, MAGIC);
    const u64 negMp = pack2(-MAGIC, -MAGIC);
    const u64 nOne  = pack2(-1.0f, -1.0f);
    __syncthreads();

    // ---- pass 1: own chunk aggregate via separability ----
    const u64* xs = (const u64*)(shx + w * Lq);
    {
        float ps = 0.0f;
#pragma unroll
        for (int j = 0; j < 4; ++j) {
            float lo, hi; unpack2(xs[4 * l + j], lo, hi);
            ps += lo;
        }
#pragma unroll
        for (int o = 16; o > 0; o >>= 1) ps += __shfl_xor_sync(0xffffffffu, ps, o);

        u64 racc2 = 0ull;
#pragma unroll 16
        for (int s = 0; s < Lq; ++s) {
            u64 u2 = fma2(xs[s], we2p, be2p);
            racc2 = add2(racc2, add2(add2(u2, Mp), negMp));   // += rint(u), exact
        }
        u64 t1 = fma2(we2p, pack2(ps, ps), beLp);
        u64 t2 = fma2(racc2, nOne, t1);
        u64 agg2 = fma2(om2p, t2, 0ull);
        *(u64*)(g_part + ((size_t)(b << 5) + c) * Hq + h0) = agg2;
    }
    __syncthreads();

    // ---- shallow per-row barrier (self-resetting, no memset needed) ----
    if (t == 0) {
        asm volatile("red.release.gpu.global.add.u32 [%0], %1;"
                     :: "l"(&g_arrive[b]), "r"(1u) : "memory");
        unsigned v;
        do {
            asm volatile("ld.global.acquire.gpu.u32 %0, [%1];"
                         : "=r"(v) : "l"(&g_arrive[b]) : "memory");
            if (v >= (unsigned)BPR) break;
            __nanosleep(40);
        } while (true);
        // Depart: the 8th block to leave resets both counters for the next launch.
        unsigned old = atomicAdd(&g_depart[b], 1u);
        if (old == (unsigned)(BPR - 1)) {
            g_arrive[b] = 0u;
            g_depart[b] = 0u;
        }
    }
    __syncthreads();

    // ---- carry: ascending sum of preceding chunk aggregates (L2-resident) ----
    float a0 = 0.f, a1 = 0.f;
    const float2* gp = (const float2*)(g_part + (size_t)(b << 5) * Hq + h0);
    for (int cc = 0; cc < c; ++cc) {
        float2 v = __ldg(gp + cc * (Hq / 2));
        a0 += v.x; a1 += v.y;
    }
    u64 acc2 = pack2(a0, a1);

    // ---- pass 2: carry-seeded scan, 2 channels/lane, STG.64 streaming ----
    char* hp = (char*)(hseq + ((size_t)b * Sq + (size_t)c * Lq) * Hq + h0);
#pragma unroll 8
    for (int s = 0; s < Lq; ++s) {
        u64 x2 = xs[s];                             // LDS.64 broadcast {x,x}
        u64 u2 = fma2(x2, we2p, be2p);
        u64 k2 = add2(add2(u2, Mp), negMp);         // rint(u), exact
        u64 f2 = fma2(k2, nOne, u2);                // u - k (exact subtract)
        acc2 = fma2(om2p, f2, acc2);
        __stcs((long long*)(hp + (size_t)s * (Hq * 4)), (long long)acc2);
    }

    // ---- output head: chunk 31's final accumulators are ph[b][h0], ph[b][h0+1] ----
    if (c == Cq - 1) {
        float p0, p1; unpack2(acc2, p0, p1);
        float tv;
        tv = p0 * W_r[2 * Hq + h0];
        tv = fmaf(cosf(p0), W_r[h0], tv);
        tv = fmaf(sinf(p0), W_r[Hq + h0], tv);
        tv = fmaf(p1, W_r[2 * Hq + h0 + 1], tv);
        tv = fmaf(cosf(p1), W_r[h0 + 1], tv);
        tv = fmaf(sinf(p1), W_r[Hq + h0 + 1], tv);
#pragma unroll
        for (int o = 16; o > 0; o >>= 1)
            tv += __shfl_down_sync(0xffffffffu, tv, o);
        if (l == 0) out[b] = tv + b_r[0];
    }
}

extern "C" void kernel_launch(void* const* d_in, const int* in_sizes, int n_in,
                              void* d_out, int out_size) {
    const float* x     = (const float*)d_in[0];
    const float* W_e   = (const float*)d_in[1];
    const float* b_e   = (const float*)d_in[2];
    const float* omega = (const float*)d_in[3];
    const float* W_r   = (const float*)d_in[4];
    const float* b_r   = (const float*)d_in[5];

    float* out  = (float*)d_out;        // out = B floats
    float* hseq = (float*)d_out + Bq;   // then Hseq = B*S*H floats

    k_fused<<<(Bq * Cq) / CPB, 128>>>(x, W_e, b_e, omega, W_r, b_r, out, hseq);
}

// round 9
// speedup vs baseline: 1.2229x; 1.0246x over previous
#include <cuda_runtime.h>
#include <cstddef>

#define Bq 256
#define Sq 4096
#define Hq 64
#define Cq 32            // chunks along S
#define Lq (Sq / Cq)     // 128 elements per chunk
#define CPB 4            // chunks per block (1 per warp)
#define BPR (Cq / CPB)   // blocks per row = 8

// Per-(b,chunk,h) chunk aggregates. 2 MB, L2-resident.
__device__ __align__(16) float g_part[(size_t)Bq * Cq * Hq];
// Self-resetting per-row barrier counters (zero at load; each launch restores zero).
__device__ unsigned g_arrive[Bq];
__device__ unsigned g_depart[Bq];

typedef unsigned long long u64;

__device__ __forceinline__ u64 pack2(float lo, float hi) {
    u64 r; asm("mov.b64 %0, {%1, %2};" : "=l"(r) : "f"(lo), "f"(hi)); return r;
}
__device__ __forceinline__ void unpack2(u64 v, float& lo, float& hi) {
    asm("mov.b64 {%0, %1}, %2;" : "=f"(lo), "=f"(hi) : "l"(v));
}
__device__ __forceinline__ void unpack2u(u64 v, unsigned& lo, unsigned& hi) {
    asm("mov.b64 {%0, %1}, %2;" : "=r"(lo), "=r"(hi) : "l"(v));
}
__device__ __forceinline__ u64 fma2(u64 a, u64 b, u64 c) {
    u64 d; asm("fma.rn.f32x2 %0, %1, %2, %3;" : "=l"(d) : "l"(a), "l"(b), "l"(c)); return d;
}
__device__ __forceinline__ u64 add2(u64 a, u64 b) {
    u64 d; asm("add.rn.f32x2 %0, %1, %2;" : "=l"(d) : "l"(a), "l"(b)); return d;
}

#define MAGIC 12582912.0f        // 1.5*2^23
#define MAGIC_BITS 0x4B400000u   // bit pattern of MAGIC; bits(MAGIC+k) = MAGIC_BITS + k

// One fused kernel. Block = 128 threads = 4 warps; warp w owns chunk c0+w.
// Lane l owns channels h = 2l, 2l+1 (packed f32x2) in both passes.
__global__ void __launch_bounds__(128) k_fused(const float* __restrict__ x,
                                               const float* __restrict__ W_e,
                                               const float* __restrict__ b_e,
                                               const float* __restrict__ omega,
                                               const float* __restrict__ W_r,
                                               const float* __restrict__ b_r,
                                               float* __restrict__ out,
                                               float* __restrict__ hseq) {
    __shared__ float4 shx[CPB * (Lq / 2)];  // {x_s,x_s,x_{s+1},x_{s+1}} per float4
    const int t  = threadIdx.x;
    const int w  = t >> 5;              // warp -> chunk within quad
    const int l  = t & 31;
    const int q  = blockIdx.x;
    const int b  = q >> 3;
    const int c0 = (q & (BPR - 1)) * CPB;
    const int c  = c0 + w;
    const int h0 = 2 * l;

    // ---- stage 512 contiguous floats (4 chunks), duplicated pairs for LDS.128 ----
    {
        const float4* xg = (const float4*)(x + (size_t)b * Sq + (size_t)c0 * Lq);
        float4 v = __ldg(xg + t);       // t = 0..127 covers 512 floats
        shx[2 * t + 0] = make_float4(v.x, v.x, v.y, v.y);
        shx[2 * t + 1] = make_float4(v.z, v.z, v.w, v.w);
    }

    const float INV_2PI = 0.15915494309189535f;
    const float TWO_PI  = 6.283185307179586f;
    const float we_lo = W_e[h0] * INV_2PI,  we_hi = W_e[h0 + 1] * INV_2PI;
    const float be_lo = b_e[h0] * INV_2PI,  be_hi = b_e[h0 + 1] * INV_2PI;
    const u64 we2p  = pack2(we_lo, we_hi);
    const u64 be2p  = pack2(be_lo, be_hi);
    const u64 om2p  = pack2(omega[h0] * TWO_PI, omega[h0 + 1] * TWO_PI);
    const u64 beLp  = pack2((float)Lq * be_lo, (float)Lq * be_hi);
    const u64 Mp    = pack2(MAGIC, MAGIC);
    const u64 negMp = pack2(-MAGIC, -MAGIC);
    const u64 nOne  = pack2(-1.0f, -1.0f);
    __syncthreads();

    const float4* xs4 = shx + w * (Lq / 2);

    // ---- pass 1: chunk aggregate; rint-sum via integer bits accumulation ----
    {
        // Sum(x) over the chunk: lane sums 4 distinct s-values, warp xor-reduce.
        float4 xa = xs4[2 * l], xb = xs4[2 * l + 1];
        float ps = (xa.x + xa.z) + (xb.x + xb.z);
#pragma unroll
        for (int o = 16; o > 0; o >>= 1) ps += __shfl_xor_sync(0xffffffffu, ps, o);

        unsigned ra_lo = 0u, ra_hi = 0u;     // bits accumulators (alu pipe)
#pragma unroll 16
        for (int j = 0; j < Lq / 2; ++j) {
            float4 xv = xs4[j];
            u64 x2a = pack2(xv.x, xv.y);
            u64 x2b = pack2(xv.z, xv.w);
            u64 va = add2(fma2(x2a, we2p, be2p), Mp);   // MAGIC + k, exact
            u64 vb = add2(fma2(x2b, we2p, be2p), Mp);
            unsigned alo, ahi, blo, bhi;
            unpack2u(va, alo, ahi);
            unpack2u(vb, blo, bhi);
            ra_lo += alo + blo;
            ra_hi += ahi + bhi;
        }
        // Sum(k) = (Sum(bits) - L*MAGIC_BITS) mod 2^32, exact small integer.
        int ks_lo = (int)(ra_lo - (unsigned)Lq * MAGIC_BITS);
        int ks_hi = (int)(ra_hi - (unsigned)Lq * MAGIC_BITS);
        u64 ksum2 = pack2((float)ks_lo, (float)ks_hi);
        // agg = om2 * (we2*sx + L*be2 - ksum)
        u64 t1 = fma2(we2p, pack2(ps, ps), beLp);
        u64 t2 = fma2(ksum2, nOne, t1);
        u64 agg2 = fma2(om2p, t2, 0ull);
        *(u64*)(g_part + ((size_t)(b << 5) + c) * Hq + h0) = agg2;
    }
    __syncthreads();

    // ---- shallow per-row barrier (self-resetting) ----
    if (t == 0) {
        asm volatile("red.release.gpu.global.add.u32 [%0], %1;"
                     :: "l"(&g_arrive[b]), "r"(1u) : "memory");
        unsigned v;
        do {
            asm volatile("ld.global.acquire.gpu.u32 %0, [%1];"
                         : "=r"(v) : "l"(&g_arrive[b]) : "memory");
            if (v >= (unsigned)BPR) break;
            __nanosleep(40);
        } while (true);
        unsigned old = atomicAdd(&g_depart[b], 1u);
        if (old == (unsigned)(BPR - 1)) {
            g_arrive[b] = 0u;
            g_depart[b] = 0u;
        }
    }
    __syncthreads();

    // ---- carry: ascending sum of preceding chunk aggregates (L2-resident) ----
    float a0 = 0.f, a1 = 0.f;
    const float2* gp = (const float2*)(g_part + (size_t)(b << 5) * Hq + h0);
    for (int cc = 0; cc < c; ++cc) {
        float2 v = __ldg(gp + cc * (Hq / 2));
        a0 += v.x; a1 += v.y;
    }
    u64 acc2 = pack2(a0, a1);

    // ---- pass 2: carry-seeded scan; LDS.128 = 2 steps; STG.64 streaming ----
    char* hp = (char*)(hseq + ((size_t)b * Sq + (size_t)c * Lq) * Hq + h0);
#pragma unroll 8
    for (int j = 0; j < Lq / 2; ++j) {
        float4 xv = xs4[j];
        {
            u64 x2 = pack2(xv.x, xv.y);
            u64 u2 = fma2(x2, we2p, be2p);
            u64 k2 = add2(add2(u2, Mp), negMp);     // rint(u), exact
            acc2 = fma2(om2p, fma2(k2, nOne, u2), acc2);
            __stcs((long long*)(hp + (size_t)(2 * j) * (Hq * 4)), (long long)acc2);
        }
        {
            u64 x2 = pack2(xv.z, xv.w);
            u64 u2 = fma2(x2, we2p, be2p);
            u64 k2 = add2(add2(u2, Mp), negMp);
            acc2 = fma2(om2p, fma2(k2, nOne, u2), acc2);
            __stcs((long long*)(hp + (size_t)(2 * j + 1) * (Hq * 4)), (long long)acc2);
        }
    }

    // ---- output head: chunk 31's final accumulators are ph[b][h0], ph[b][h0+1] ----
    if (c == Cq - 1) {
        float p0, p1; unpack2(acc2, p0, p1);
        float tv;
        tv = p0 * W_r[2 * Hq + h0];
        tv = fmaf(cosf(p0), W_r[h0], tv);
        tv = fmaf(sinf(p0), W_r[Hq + h0], tv);
        tv = fmaf(p1, W_r[2 * Hq + h0 + 1], tv);
        tv = fmaf(cosf(p1), W_r[h0 + 1], tv);
        tv = fmaf(sinf(p1), W_r[Hq + h0 + 1], tv);
#pragma unroll
        for (int o = 16; o > 0; o >>= 1)
            tv += __shfl_down_sync(0xffffffffu, tv, o);
        if (l == 0) out[b] = tv + b_r[0];
    }
}

extern "C" void kernel_launch(void* const* d_in, const int* in_sizes, int n_in,
                              void* d_out, int out_size) {
    const float* x     = (const float*)d_in[0];
    const float* W_e   = (const float*)d_in[1];
    const float* b_e   = (const float*)d_in[2];
    const float* omega = (const float*)d_in[3];
    const float* W_r   = (const float*)d_in[4];
    const float* b_r   = (const float*)d_in[5];

    float* out  = (float*)d_out;        // out = B floats
    float* hseq = (float*)d_out + Bq;   // then Hseq = B*S*H floats

    k_fused<<<(Bq * Cq) / CPB, 128>>>(x, W_e, b_e, omega, W_r, b_r, out, hseq);
}

// round 10
// speedup vs baseline: 1.2244x; 1.0012x over previous
#include <cuda_runtime.h>
#include <cstddef>

#define Bq 256
#define Sq 4096
#define Hq 64
#define Cq 32            // chunks along S
#define Lq (Sq / Cq)     // 128 elements per chunk
#define CPB 4            // chunks per block (1 per warp)
#define BPR (Cq / CPB)   // blocks per row = 8

// Per-(b,chunk,h) chunk aggregates. 2 MB, L2-resident.
__device__ __align__(16) float g_part[(size_t)Bq * Cq * Hq];
// Self-resetting per-row barrier counters (zero at load; each launch restores zero).
__device__ unsigned g_arrive[Bq];
__device__ unsigned g_depart[Bq];

typedef unsigned long long u64;

__device__ __forceinline__ u64 pack2(float lo, float hi) {
    u64 r; asm("mov.b64 %0, {%1, %2};" : "=l"(r) : "f"(lo), "f"(hi)); return r;
}
__device__ __forceinline__ void unpack2(u64 v, float& lo, float& hi) {
    asm("mov.b64 {%0, %1}, %2;" : "=f"(lo), "=f"(hi) : "l"(v));
}
__device__ __forceinline__ void unpack2u(u64 v, unsigned& lo, unsigned& hi) {
    asm("mov.b64 {%0, %1}, %2;" : "=r"(lo), "=r"(hi) : "l"(v));
}
__device__ __forceinline__ u64 fma2(u64 a, u64 b, u64 c) {
    u64 d; asm("fma.rn.f32x2 %0, %1, %2, %3;" : "=l"(d) : "l"(a), "l"(b), "l"(c)); return d;
}
__device__ __forceinline__ u64 add2(u64 a, u64 b) {
    u64 d; asm("add.rn.f32x2 %0, %1, %2;" : "=l"(d) : "l"(a), "l"(b)); return d;
}

#define MAGIC 12582912.0f        // 1.5*2^23
#define MAGIC_BITS 0x4B400000u   // bits(MAGIC + k) = MAGIC_BITS + k for integer k
#define HLq (Lq / 2)             // 64 steps per half-warp

// Block = 128 threads = 4 warps; warp w owns chunk c0+w.
// Warp split s-wise: lanes 0-15 do s in [0,64), lanes 16-31 do s in [64,128).
// Each lane owns 4 channels h0..h0+3 as two f32x2 chains -> STG.128 per step.
__global__ void __launch_bounds__(128) k_fused(const float* __restrict__ x,
                                               const float* __restrict__ W_e,
                                               const float* __restrict__ b_e,
                                               const float* __restrict__ omega,
                                               const float* __restrict__ W_r,
                                               const float* __restrict__ b_r,
                                               float* __restrict__ out,
                                               float* __restrict__ hseq) {
    __shared__ float4 shx[CPB * (Lq / 2)];  // {x_s,x_s,x_{s+1},x_{s+1}} per float4
    const int t  = threadIdx.x;
    const int w  = t >> 5;              // warp -> chunk within quad
    const int l  = t & 31;
    const int hh = l >> 4;              // s-half: 0 or 1
    const int li = l & 15;
    const int h0 = 4 * li;              // 4 channels per lane
    const int q  = blockIdx.x;
    const int b  = q >> 3;
    const int c0 = (q & (BPR - 1)) * CPB;
    const int c  = c0 + w;

    // ---- stage 512 contiguous floats (4 chunks), duplicated pairs for LDS.128 ----
    {
        const float4* xg = (const float4*)(x + (size_t)b * Sq + (size_t)c0 * Lq);
        float4 v = __ldg(xg + t);       // t = 0..127 covers 512 floats
        shx[2 * t + 0] = make_float4(v.x, v.x, v.y, v.y);
        shx[2 * t + 1] = make_float4(v.z, v.z, v.w, v.w);
    }

    const float INV_2PI = 0.15915494309189535f;
    const float TWO_PI  = 6.283185307179586f;
    const float we0 = W_e[h0]     * INV_2PI, we1 = W_e[h0 + 1] * INV_2PI;
    const float we2 = W_e[h0 + 2] * INV_2PI, we3 = W_e[h0 + 3] * INV_2PI;
    const float be0 = b_e[h0]     * INV_2PI, be1 = b_e[h0 + 1] * INV_2PI;
    const float be2 = b_e[h0 + 2] * INV_2PI, be3 = b_e[h0 + 3] * INV_2PI;
    const u64 weA = pack2(we0, we1), weB = pack2(we2, we3);
    const u64 beA = pack2(be0, be1), beB = pack2(be2, be3);
    const u64 omA = pack2(omega[h0] * TWO_PI,     omega[h0 + 1] * TWO_PI);
    const u64 omB = pack2(omega[h0 + 2] * TWO_PI, omega[h0 + 3] * TWO_PI);
    const u64 Mp    = pack2(MAGIC, MAGIC);
    const u64 negMp = pack2(-MAGIC, -MAGIC);
    const u64 nOne  = pack2(-1.0f, -1.0f);
    __syncthreads();

    // Half-warp's 32 x-pairs (covers its 64 s-steps).
    const float4* xs4 = shx + w * (Lq / 2) + hh * (HLq / 2);

    // ---- pass 1: half-chunk aggregates via separability (per chain) ----
    u64 aggA, aggB;
    {
        float psx = 0.0f;                       // Sum(x) over own half (all lanes identical)
        unsigned raA_lo = 0u, raA_hi = 0u;      // rint-bits accumulators, chain A
        unsigned raB_lo = 0u, raB_hi = 0u;      // chain B
#pragma unroll 8
        for (int jp = 0; jp < HLq / 2; ++jp) {
            float4 xv = xs4[jp];
            psx += xv.x + xv.z;
            u64 x2a = pack2(xv.x, xv.y);
            u64 x2b = pack2(xv.z, xv.w);
            u64 vaA = add2(fma2(x2a, weA, beA), Mp);
            u64 vbA = add2(fma2(x2b, weA, beA), Mp);
            u64 vaB = add2(fma2(x2a, weB, beB), Mp);
            u64 vbB = add2(fma2(x2b, weB, beB), Mp);
            unsigned u0, u1;
            unpack2u(vaA, u0, u1); raA_lo += u0; raA_hi += u1;
            unpack2u(vbA, u0, u1); raA_lo += u0; raA_hi += u1;
            unpack2u(vaB, u0, u1); raB_lo += u0; raB_hi += u1;
            unpack2u(vbB, u0, u1); raB_lo += u0; raB_hi += u1;
        }
        const unsigned sub = (unsigned)HLq * MAGIC_BITS;
        u64 ksA = pack2((float)(int)(raA_lo - sub), (float)(int)(raA_hi - sub));
        u64 ksB = pack2((float)(int)(raB_lo - sub), (float)(int)(raB_hi - sub));
        u64 hs2 = pack2(psx, psx);
        u64 beLA = pack2((float)HLq * be0, (float)HLq * be1);
        u64 beLB = pack2((float)HLq * be2, (float)HLq * be3);
        u64 tA = fma2(ksA, nOne, fma2(weA, hs2, beLA));
        u64 tB = fma2(ksB, nOne, fma2(weB, hs2, beLB));
        aggA = fma2(omA, tA, 0ull);
        aggB = fma2(omB, tB, 0ull);
    }

    // Exchange halves: other = the other s-half's aggregate (same channels).
    u64 othA = __shfl_xor_sync(0xffffffffu, aggA, 16);
    u64 othB = __shfl_xor_sync(0xffffffffu, aggB, 16);
    // Publish full-chunk aggregate (lanes 0-15 only, 256B coalesced STG.128).
    if (hh == 0) {
        ulonglong2 fullv;
        fullv.x = add2(aggA, othA);
        fullv.y = add2(aggB, othB);
        *(ulonglong2*)(g_part + ((size_t)(b << 5) + c) * Hq + h0) = fullv;
    }
    __syncthreads();

    // ---- shallow per-row barrier (self-resetting) ----
    if (t == 0) {
        asm volatile("red.release.gpu.global.add.u32 [%0], %1;"
                     :: "l"(&g_arrive[b]), "r"(1u) : "memory");
        unsigned v;
        do {
            asm volatile("ld.global.acquire.gpu.u32 %0, [%1];"
                         : "=r"(v) : "l"(&g_arrive[b]) : "memory");
            if (v >= (unsigned)BPR) break;
            __nanosleep(40);
        } while (true);
        unsigned old = atomicAdd(&g_depart[b], 1u);
        if (old == (unsigned)(BPR - 1)) {
            g_arrive[b] = 0u;
            g_depart[b] = 0u;
        }
    }
    __syncthreads();

    // ---- carry: ascending sum of preceding chunk aggregates (L2-resident) ----
    u64 accA = 0ull, accB = 0ull;
    {
        const float4* gp = (const float4*)(g_part + (size_t)(b << 5) * Hq + h0);
        float a0 = 0.f, a1 = 0.f, a2 = 0.f, a3 = 0.f;
        for (int cc = 0; cc < c; ++cc) {
            float4 v = __ldg(gp + cc * (Hq / 4));
            a0 += v.x; a1 += v.y; a2 += v.z; a3 += v.w;
        }
        accA = pack2(a0, a1);
        accB = pack2(a2, a3);
    }
    // Upper half additionally seeds with the lower half's aggregate.
    if (hh) {
        accA = add2(accA, othA);
        accB = add2(accB, othB);
    }

    // ---- pass 2: carry-seeded scan; LDS.128 = 2 steps; STG.128 per step ----
    char* hp = (char*)(hseq + ((size_t)b * Sq + (size_t)c * Lq + (size_t)hh * HLq) * Hq + h0);
#pragma unroll 8
    for (int jp = 0; jp < HLq / 2; ++jp) {
        float4 xv = xs4[jp];
        {
            u64 x2 = pack2(xv.x, xv.y);
            u64 uA = fma2(x2, weA, beA);
            u64 kA = add2(add2(uA, Mp), negMp);
            accA = fma2(omA, fma2(kA, nOne, uA), accA);
            u64 uB = fma2(x2, weB, beB);
            u64 kB = add2(add2(uB, Mp), negMp);
            accB = fma2(omB, fma2(kB, nOne, uB), accB);
            ulonglong2 stv; stv.x = accA; stv.y = accB;
            __stcs((ulonglong2*)(hp + (size_t)(2 * jp) * (Hq * 4)), stv);
        }
        {
            u64 x2 = pack2(xv.z, xv.w);
            u64 uA = fma2(x2, weA, beA);
            u64 kA = add2(add2(uA, Mp), negMp);
            accA = fma2(omA, fma2(kA, nOne, uA), accA);
            u64 uB = fma2(x2, weB, beB);
            u64 kB = add2(add2(uB, Mp), negMp);
            accB = fma2(omB, fma2(kB, nOne, uB), accB);
            ulonglong2 stv; stv.x = accA; stv.y = accB;
            __stcs((ulonglong2*)(hp + (size_t)(2 * jp + 1) * (Hq * 4)), stv);
        }
    }

    // ---- output head: chunk 31's upper half ends with ph[b][h0..h0+3] ----
    if (c == Cq - 1 && hh == 1) {
        float p0, p1, p2, p3;
        unpack2(accA, p0, p1);
        unpack2(accB, p2, p3);
        float tv;
        tv = p0 * W_r[2 * Hq + h0];
        tv = fmaf(cosf(p0), W_r[h0], tv);
        tv = fmaf(sinf(p0), W_r[Hq + h0], tv);
        tv = fmaf(p1, W_r[2 * Hq + h0 + 1], tv);
        tv = fmaf(cosf(p1), W_r[h0 + 1], tv);
        tv = fmaf(sinf(p1), W_r[Hq + h0 + 1], tv);
        tv = fmaf(p2, W_r[2 * Hq + h0 + 2], tv);
        tv = fmaf(cosf(p2), W_r[h0 + 2], tv);
        tv = fmaf(sinf(p2), W_r[Hq + h0 + 2], tv);
        tv = fmaf(p3, W_r[2 * Hq + h0 + 3], tv);
        tv = fmaf(cosf(p3), W_r[h0 + 3], tv);
        tv = fmaf(sinf(p3), W_r[Hq + h0 + 3], tv);
#pragma unroll
        for (int o = 8; o > 0; o >>= 1)
            tv += __shfl_down_sync(0xFFFF0000u, tv, o, 16);
        if (l == 16) out[b] = tv + b_r[0];
    }
}

extern "C" void kernel_launch(void* const* d_in, const int* in_sizes, int n_in,
                              void* d_out, int out_size) {
    const float* x     = (const float*)d_in[0];
    const float* W_e   = (const float*)d_in[1];
    const float* b_e   = (const float*)d_in[2];
    const float* omega = (const float*)d_in[3];
    const float* W_r   = (const float*)d_in[4];
    const float* b_r   = (const float*)d_in[5];

    float* out  = (float*)d_out;        // out = B floats
    float* hseq = (float*)d_out + Bq;   // then Hseq = B*S*H floats

    k_fused<<<(Bq * Cq) / CPB, 128>>>(x, W_e, b_e, omega, W_r, b_r, out, hseq);
}